// round 15
// baseline (speedup 1.0000x reference)
#include <cuda_runtime.h>
#include <math.h>

typedef unsigned long long u64;

#define NG 8
#define NT 2048
#define NH 2048
#define NE 8
#define CAP 320
#define NTOK (NG * NT)        // 16384
#define TPW 4                 // tokens per warp
#define TPBK 32               // tokens per block (8 warps * 4)
#define NBLK (NTOK / TPBK)    // 512 (3 CTAs/SM resident -> 24 warps/SM)
#define BPG (NBLK / NG)       // 64 blocks per group (power of 2)
#define THREADS 256
#define NITER 16              // H chunks of 128 floats

// scratch: argmax ids; per-group completion counters.
// g_cnt is tested modulo BPG -> never needs resetting across graph replays.
__device__ unsigned char g_expert_id[NTOK];
__device__ unsigned int  g_cnt[NG];

__device__ __forceinline__ void fma2(u64& acc, u64 a, u64 b) {
    asm("fma.rn.f32x2 %0, %1, %2, %0;" : "+l"(acc) : "l"(a), "l"(b));
}
__device__ __forceinline__ u64 add2(u64 a, u64 b) {
    u64 r; asm("add.rn.f32x2 %0, %1, %2;" : "=l"(r) : "l"(a), "l"(b));
    return r;
}
__device__ __forceinline__ u64 pack2(float lo, float hi) {
    u64 r; asm("mov.b64 %0, {%1, %2};" : "=l"(r) : "f"(lo), "f"(hi));
    return r;
}
__device__ __forceinline__ u64 dup2(float v) { return pack2(v, v); }
__device__ __forceinline__ void unpack2(u64 v, float& lo, float& hi) {
    asm("mov.b64 {%0, %1}, %2;" : "=f"(lo), "=f"(hi) : "l"(v));
}

// ---------------------------------------------------------------------------
// Capacity epilogue: per-group inclusive cumsum of assignments; zero the
// over-capacity one-hot entries. Run by the LAST router block of each group.
// ---------------------------------------------------------------------------
__device__ void capacity_epilogue(int g, float* __restrict__ out) {
    const int tid = threadIdx.x;           // 256
    const int lane = tid & 31, wrp = tid >> 5;

    u64 ids = ((const u64*)g_expert_id)[g * (NT / 8) + tid];

    int c[NE], s[NE];
#pragma unroll
    for (int e = 0; e < NE; e++) c[e] = 0;
#pragma unroll
    for (int i = 0; i < 8; i++) {
        int e = (int)((ids >> (8 * i)) & 0xFFULL);
#pragma unroll
        for (int ee = 0; ee < NE; ee++) c[ee] += (e == ee);
    }
#pragma unroll
    for (int e = 0; e < NE; e++) s[e] = c[e];
#pragma unroll
    for (int off = 1; off < 32; off <<= 1) {
#pragma unroll
        for (int e = 0; e < NE; e++) {
            int v = __shfl_up_sync(0xffffffffu, s[e], off);
            if (lane >= off) s[e] += v;
        }
    }

    __shared__ int wt[8][NE];
    if (lane == 31) {
#pragma unroll
        for (int e = 0; e < NE; e++) wt[wrp][e] = s[e];
    }
    __syncthreads();
    if (tid < NE) {            // exclusive scan of 8 warp totals
        int run = 0;
#pragma unroll
        for (int w = 0; w < 8; w++) {
            int v = wt[w][tid];
            wt[w][tid] = run;
            run += v;
        }
    }
    __syncthreads();

    int base[NE];
#pragma unroll
    for (int e = 0; e < NE; e++) base[e] = (s[e] - c[e]) + wt[wrp][e];

    int run2[NE];
#pragma unroll
    for (int e = 0; e < NE; e++) run2[e] = 0;

    const size_t tok0 = (size_t)g * NT + (size_t)tid * 8;
#pragma unroll
    for (int i = 0; i < 8; i++) {
        int e = (int)((ids >> (8 * i)) & 0xFFULL);
#pragma unroll
        for (int ee = 0; ee < NE; ee++) {
            int inc = (e == ee);
            run2[ee] += inc;
            if (inc && (base[ee] + run2[ee] > CAP))
                out[(tok0 + i) * NE + ee] = 0.0f;
        }
    }
}

// ---------------------------------------------------------------------------
// Router kernel (R4 body at occupancy 3). warp = 4 tokens, lanes span H
// (coalesced LDG.128), front-batched 4 independent loads per iteration.
// 3 CTAs/SM x 8 warps = 24 warps (6/SMSP): enough out-of-phase warps to
// cover both DRAM-latency and intra-compute dependency stalls that capped
// the 2-CTA variants at ~50% DRAM. TPW=4 keeps regs ~78 < 85-reg cap.
// W in smem, expert-pair packed, streamed per-j (4 u64 live).
// acc[t][p] holds packed (logit[2p], logit[2p+1]) per token.
// ---------------------------------------------------------------------------
__global__ __launch_bounds__(THREADS, 3)
void router_kernel(const float4* __restrict__ hs4,
                   const float* __restrict__ W,
                   const float* __restrict__ bias,
                   float* __restrict__ out) {
    extern __shared__ char smem[];
    u64*   shw      = (u64*)smem;                       // 8192 u64 = 64 KB
    float* sh_logit = (float*)(shw + NE * NH / 2);      // 32*9
    float* sh_bias  = sh_logit + TPBK * 9;              // 8
    int*   sh_arg   = (int*)(sh_bias + 8);              // 32

    const int tid  = threadIdx.x;
    const int lane = tid & 31, warp = tid >> 5;

    // W permuted for expert-pair packing:
    // word[(i*16 + j*4 + p)*32 + l] = (W[2p][h], W[2p+1][h]),
    //   h = i*128 + l*4 + j  -> per-(i,j) the 4 pair-words are at
    // consecutive-lane u64 addresses (conflict-free LDS.64).
    {
        const float2* W2 = (const float2*)W;
        float* shwf = (float*)shw;
        for (int u = tid; u < NE * NH / 2; u += THREADS) {
            int e = u >> 10;
            int h = (u & 1023) * 2;           // even h; covers (h, h+1)
            float2 w = W2[u];
            int i = h >> 7, l = (h >> 2) & 31, j = h & 3;
            int p = e >> 1, pos = e & 1;
            int w0 = ((i * 16 + j * 4 + p) << 5) + l;
            int w1 = ((i * 16 + (j + 1) * 4 + p) << 5) + l;
            shwf[w0 * 2 + pos] = w.x;
            shwf[w1 * 2 + pos] = w.y;
        }
    }
    if (tid < 8) sh_bias[tid] = bias[tid];
    __syncthreads();

    const int tok0 = blockIdx.x * TPBK + warp * TPW;
    const float4* xp = hs4 + (size_t)tok0 * (NH / 4) + lane;

    u64 acc[TPW][4];
#pragma unroll
    for (int t = 0; t < TPW; t++)
#pragma unroll
        for (int p = 0; p < 4; p++) acc[t][p] = 0ULL;

#pragma unroll 1
    for (int i = 0; i < NITER; i++) {
        // front-batched: 4 independent LDG.128 (512B coalesced each)
        float4 xv[TPW];
#pragma unroll
        for (int t = 0; t < TPW; t++)
            xv[t] = xp[t * (NH / 4) + i * 32];

#pragma unroll
        for (int j = 0; j < 4; j++) {
            u64 w0 = shw[((i * 16 + j * 4 + 0) << 5) + lane];
            u64 w1 = shw[((i * 16 + j * 4 + 1) << 5) + lane];
            u64 w2 = shw[((i * 16 + j * 4 + 2) << 5) + lane];
            u64 w3 = shw[((i * 16 + j * 4 + 3) << 5) + lane];
#pragma unroll
            for (int t = 0; t < TPW; t++) {
                float xs = (j == 0) ? xv[t].x : (j == 1) ? xv[t].y
                         : (j == 2) ? xv[t].z : xv[t].w;
                u64 xd = dup2(xs);
                fma2(acc[t][0], xd, w0);
                fma2(acc[t][1], xd, w1);
                fma2(acc[t][2], xd, w2);
                fma2(acc[t][3], xd, w3);
            }
        }
    }

    // butterfly-reduce packed (token, expert-pair) accumulators across warp
#pragma unroll
    for (int off = 16; off; off >>= 1) {
#pragma unroll
        for (int t = 0; t < TPW; t++)
#pragma unroll
            for (int p = 0; p < 4; p++)
                acc[t][p] = add2(acc[t][p],
                                 __shfl_xor_sync(0xffffffffu, acc[t][p], off));
    }
    if (lane == 0) {
#pragma unroll
        for (int t = 0; t < TPW; t++)
#pragma unroll
            for (int p = 0; p < 4; p++) {
                float lo, hi;
                unpack2(acc[t][p], lo, hi);
                sh_logit[(warp * TPW + t) * 9 + 2 * p]     = lo + sh_bias[2 * p];
                sh_logit[(warp * TPW + t) * 9 + 2 * p + 1] = hi + sh_bias[2 * p + 1];
            }
    }
    __syncthreads();

    // softmax stats + argmax (first-max semantics matches jnp.argmax)
    if (tid < TPBK) {
        const float* l = sh_logit + tid * 9;
        float best = l[0]; int bi = 0;
#pragma unroll
        for (int e = 1; e < NE; e++) {
            float v = l[e];
            if (v > best) { best = v; bi = e; }
        }
        float s = 0.f;
#pragma unroll
        for (int e = 0; e < NE; e++) s += expf(l[e] - best);
        sh_arg[tid] = bi;
        int gt = blockIdx.x * TPBK + tid;
        out[(size_t)NTOK * NE + gt] = 1.0f / s;      // max router prob
        g_expert_id[gt] = (unsigned char)bi;
    }
    __syncthreads();

    // one-hot (pre-capacity) + logits: 256 elems (32 tokens x 8 experts)
    {
        int t = tid >> 3, e = tid & 7;
        int gt = blockIdx.x * TPBK + t;
        out[(size_t)gt * NE + e] = (e == sh_arg[t]) ? 1.0f : 0.0f;
        out[(size_t)NTOK * NE + NTOK + (size_t)gt * NE + e] = sh_logit[t * 9 + e];
    }

    // ---- fused capacity epilogue: last block of each group runs it ----
    __threadfence();
    __syncthreads();
    __shared__ int s_last;
    if (tid == 0) {
        unsigned int v = atomicAdd(&g_cnt[blockIdx.x / BPG], 1u);
        s_last = ((v & (BPG - 1)) == (BPG - 1));
    }
    __syncthreads();
    if (s_last) {
        __threadfence();   // acquire: see all group blocks' writes
        capacity_epilogue(blockIdx.x / BPG, out);
    }
}

// ---------------------------------------------------------------------------
extern "C" void kernel_launch(void* const* d_in, const int* in_sizes, int n_in,
                              void* d_out, int out_size) {
    const float4* hs = (const float4*)d_in[0];  // [8, 2048, 2048] f32
    const float* W   = (const float*)d_in[1];   // [8, 2048] f32
    const float* b   = (const float*)d_in[2];   // [8] f32
    float* out = (float*)d_out;

    const int smem = NE * NH / 2 * 8            // W u64 (pair-packed)
                   + TPBK * 9 * 4               // logits
                   + 8 * 4                      // bias
                   + TPBK * 4;                  // argmax
    cudaFuncSetAttribute(router_kernel,
                         cudaFuncAttributeMaxDynamicSharedMemorySize, smem);

    router_kernel<<<NBLK, THREADS, smem>>>(hs, W, b, out);
}

// round 16
// speedup vs baseline: 1.2106x; 1.2106x over previous
#include <cuda_runtime.h>
#include <cuda.h>
#include <math.h>

typedef unsigned long long u64;

#define NG 8
#define NT 2048
#define NH 2048
#define NE 8
#define CAP 320
#define NTOK (NG * NT)          // 16384

// ---- TMA kernel config ----
#define T_THREADS 512
#define T_TPBK 128              // tokens per block
#define T_NBLK (NTOK / T_TPBK)  // 128 blocks -> single wave at 1 CTA/SM
#define T_BPG (T_NBLK / NG)     // 16 blocks per group (power of 2)
#define T_NITER 32              // stages of 64 h
#define T_NSTAGE 4
#define SUBB 16384              // one TMA box: 128 tokens x 128 bytes
#define STAGEB (2 * SUBB)       // 32 KB per stage (64 h)
#define SMEM_W 65536
#define STAGE_OFF SMEM_W
#define MISC_OFF (STAGE_OFF + T_NSTAGE * STAGEB)          // 196608
#define LOGIT_OFF MISC_OFF                                 // 128*9 floats
#define BIAS_OFF (LOGIT_OFF + 128 * 9 * 4)
#define ARG_OFF  (BIAS_OFF + 32)
#define MBAR_OFF ((ARG_OFF + 128 * 4 + 15) & ~15)
#define SMEM_TOTAL (MBAR_OFF + T_NSTAGE * 8)

// scratch: argmax ids; per-group completion counters (mod-tested -> no reset)
__device__ unsigned char g_expert_id[NTOK];
__device__ unsigned int  g_cnt[NG];

__device__ __forceinline__ void fma2(u64& acc, u64 a, u64 b) {
    asm("fma.rn.f32x2 %0, %1, %2, %0;" : "+l"(acc) : "l"(a), "l"(b));
}
__device__ __forceinline__ u64 add2(u64 a, u64 b) {
    u64 r; asm("add.rn.f32x2 %0, %1, %2;" : "=l"(r) : "l"(a), "l"(b));
    return r;
}
__device__ __forceinline__ u64 pack2(float lo, float hi) {
    u64 r; asm("mov.b64 %0, {%1, %2};" : "=l"(r) : "f"(lo), "f"(hi));
    return r;
}
__device__ __forceinline__ u64 dup2(float v) { return pack2(v, v); }
__device__ __forceinline__ void unpack2(u64 v, float& lo, float& hi) {
    asm("mov.b64 {%0, %1}, %2;" : "=f"(lo), "=f"(hi) : "l"(v));
}
__device__ __forceinline__ void mbar_init(unsigned mbar, unsigned count) {
    asm volatile("mbarrier.init.shared.b64 [%0], %1;" :: "r"(mbar), "r"(count)
                 : "memory");
}
__device__ __forceinline__ void mbar_expect_tx(unsigned mbar, unsigned bytes) {
    asm volatile("mbarrier.arrive.expect_tx.shared.b64 _, [%0], %1;"
                 :: "r"(mbar), "r"(bytes) : "memory");
}
__device__ __forceinline__ void mbar_wait(unsigned mbar, unsigned parity) {
    asm volatile(
        "{\n\t"
        ".reg .pred P1;\n\t"
        "WAIT_LOOP_%=:\n\t"
        "mbarrier.try_wait.parity.acquire.cta.shared::cta.b64 P1, [%0], %1, 0x989680;\n\t"
        "@P1 bra.uni WAIT_DONE_%=;\n\t"
        "bra.uni WAIT_LOOP_%=;\n\t"
        "WAIT_DONE_%=:\n\t"
        "}"
        :: "r"(mbar), "r"(parity) : "memory");
}
__device__ __forceinline__ void tma2d(unsigned dst, const CUtensorMap* map,
                                      int x, int y, unsigned mbar) {
    asm volatile(
        "cp.async.bulk.tensor.2d.shared::cta.global.tile.mbarrier::complete_tx::bytes "
        "[%0], [%1, {%2, %3}], [%4];"
        :: "r"(dst), "l"(map), "r"(x), "r"(y), "r"(mbar) : "memory");
}

// ---------------------------------------------------------------------------
// Capacity epilogue: per-group inclusive cumsum of assignments; zero
// over-capacity one-hots. First 256 threads of the block do the scan.
// ---------------------------------------------------------------------------
__device__ void capacity_epilogue(int g, float* __restrict__ out) {
    const int tid = threadIdx.x;
    const int lane = tid & 31, wrp = tid >> 5;
    __shared__ int wt[8][NE];

    u64 ids = 0;
    int c[NE], s[NE];
#pragma unroll
    for (int e = 0; e < NE; e++) { c[e] = 0; s[e] = 0; }

    if (tid < 256) {
        ids = ((const u64*)g_expert_id)[g * (NT / 8) + tid];
#pragma unroll
        for (int i = 0; i < 8; i++) {
            int e = (int)((ids >> (8 * i)) & 0xFFULL);
#pragma unroll
            for (int ee = 0; ee < NE; ee++) c[ee] += (e == ee);
        }
#pragma unroll
        for (int e = 0; e < NE; e++) s[e] = c[e];
#pragma unroll
        for (int off = 1; off < 32; off <<= 1) {
#pragma unroll
            for (int e = 0; e < NE; e++) {
                int v = __shfl_up_sync(0xffffffffu, s[e], off);
                if (lane >= off) s[e] += v;
            }
        }
        if (lane == 31) {
#pragma unroll
            for (int e = 0; e < NE; e++) wt[wrp][e] = s[e];
        }
    }
    __syncthreads();
    if (tid < NE) {
        int run = 0;
#pragma unroll
        for (int w = 0; w < 8; w++) {
            int v = wt[w][tid];
            wt[w][tid] = run;
            run += v;
        }
    }
    __syncthreads();

    if (tid < 256) {
        int base[NE];
#pragma unroll
        for (int e = 0; e < NE; e++) base[e] = (s[e] - c[e]) + wt[wrp][e];
        int run2[NE];
#pragma unroll
        for (int e = 0; e < NE; e++) run2[e] = 0;
        const size_t tok0 = (size_t)g * NT + (size_t)tid * 8;
#pragma unroll
        for (int i = 0; i < 8; i++) {
            int e = (int)((ids >> (8 * i)) & 0xFFULL);
#pragma unroll
            for (int ee = 0; ee < NE; ee++) {
                int inc = (e == ee);
                run2[ee] += inc;
                if (inc && (base[ee] + run2[ee] > CAP))
                    out[(tok0 + i) * NE + ee] = 0.0f;
            }
        }
    }
}

// ---------------------------------------------------------------------------
// TMA router kernel. x staged through a 4-deep TMA pipeline (2 UTMALDG of
// 16 KB per 32 KB stage, SW128, mbarrier completion): in-flight DRAM bytes
// are decoupled from registers and warp count. Compute: lane = token
// (lane + 32*tk, tk=0..3), warp w owns stage-local h [4w, 4w+4); x read as
// one swizzled LDS.128 per token (conflict-free phases), W smem broadcasts.
// Per-warp h-partials reduced at the end via the retired stage area.
// ---------------------------------------------------------------------------
__global__ __launch_bounds__(T_THREADS, 1)
void router_tma_kernel(const __grid_constant__ CUtensorMap tmap,
                       const float* __restrict__ W,
                       const float* __restrict__ bias,
                       float* __restrict__ out) {
    extern __shared__ __align__(1024) char smem[];
    u64*   shw      = (u64*)smem;                     // W: 64 KB, shw[h*4+p]
    float* sh_logit = (float*)(smem + LOGIT_OFF);
    float* sh_bias  = (float*)(smem + BIAS_OFF);
    int*   sh_arg   = (int*)(smem + ARG_OFF);

    const int tid  = threadIdx.x;
    const int lane = tid & 31, warp = tid >> 5;
    const unsigned smem_u = (unsigned)__cvta_generic_to_shared(smem);
    const unsigned mbar0  = smem_u + MBAR_OFF;

    // W fill: shwf[h*8 + (e>>1)*2 + (e&1)] = W[e][h]  (broadcast pair layout)
    {
        float* shwf = (float*)shw;
        const float4* W4 = (const float4*)W;
#pragma unroll
        for (int q = 0; q < 8; q++) {
            int idx4 = tid + q * T_THREADS;          // 0..4095
            float4 v = W4[idx4];
#pragma unroll
            for (int c = 0; c < 4; c++) {
                int f = idx4 * 4 + c;                // e*2048 + h
                int e = f >> 11, h = f & 2047;
                float val = (c == 0) ? v.x : (c == 1) ? v.y
                          : (c == 2) ? v.z : v.w;
                shwf[h * 8 + (e >> 1) * 2 + (e & 1)] = val;
            }
        }
    }
    if (tid < 8) sh_bias[tid] = bias[tid];
    if (tid == 0) {
#pragma unroll
        for (int s = 0; s < T_NSTAGE; s++) mbar_init(mbar0 + s * 8, 1);
    }
    asm volatile("fence.proxy.async.shared::cta;" ::: "memory");
    __syncthreads();

    const int y0 = blockIdx.x * T_TPBK;

    auto issue = [&](int s) {
        unsigned mb  = mbar0 + (s & 3) * 8;
        unsigned dst = smem_u + STAGE_OFF + (unsigned)((s & 3) * STAGEB);
        mbar_expect_tx(mb, STAGEB);
        tma2d(dst,        &tmap, s * 64,      y0, mb);
        tma2d(dst + SUBB, &tmap, s * 64 + 32, y0, mb);
    };
    if (tid == 0) {
        issue(0); issue(1); issue(2); issue(3);
    }

    u64 acc[4][4];
#pragma unroll
    for (int t = 0; t < 4; t++)
#pragma unroll
        for (int p = 0; p < 4; p++) acc[t][p] = 0ULL;

    const int sub  = warp >> 3;            // which 16KB half of the stage
    const int colb = (warp & 7) * 16;      // byte column within 128B row

#pragma unroll 1
    for (int i = 0; i < T_NITER; i++) {
        mbar_wait(mbar0 + (i & 3) * 8, (i >> 2) & 1);

        const char* st = smem + STAGE_OFF + (i & 3) * STAGEB + sub * SUBB;
        const int hbase = i * 64 + warp * 4;

        u64 wv[4][4];
#pragma unroll
        for (int hh = 0; hh < 4; hh++)
#pragma unroll
            for (int p = 0; p < 4; p++)
                wv[hh][p] = shw[(hbase + hh) * 4 + p];

#pragma unroll
        for (int tk = 0; tk < 4; tk++) {
            int t = lane + 32 * tk;
            unsigned off = (unsigned)(t * 128 + colb);
            unsigned sw  = off ^ ((off >> 3) & 0x70);
            float4 x4 = *(const float4*)(st + sw);
#pragma unroll
            for (int hh = 0; hh < 4; hh++) {
                float xs = (hh == 0) ? x4.x : (hh == 1) ? x4.y
                         : (hh == 2) ? x4.z : x4.w;
                u64 xd = dup2(xs);
                fma2(acc[tk][0], xd, wv[hh][0]);
                fma2(acc[tk][1], xd, wv[hh][1]);
                fma2(acc[tk][2], xd, wv[hh][2]);
                fma2(acc[tk][3], xd, wv[hh][3]);
            }
        }

        __syncthreads();                       // all consumed slot i&3
        if (tid == 0 && i + T_NSTAGE < T_NITER) issue(i + T_NSTAGE);
    }

    // per-warp partials -> retired stage area: part[w*512 + t*4 + p]
    {
        u64* part = (u64*)(smem + STAGE_OFF);
#pragma unroll
        for (int tk = 0; tk < 4; tk++)
#pragma unroll
            for (int p = 0; p < 4; p++)
                part[warp * (T_TPBK * 4) + (lane + 32 * tk) * 4 + p] = acc[tk][p];
    }
    __syncthreads();

    // reduce 16 warp-partials: 512 threads = (128 tokens x 4 pairs)
    {
        const u64* part = (const u64*)(smem + STAGE_OFF);
        int t = tid >> 2, p = tid & 3;
        u64 s = part[t * 4 + p];
#pragma unroll
        for (int w = 1; w < 16; w++)
            s = add2(s, part[w * (T_TPBK * 4) + t * 4 + p]);
        float lo, hi;
        unpack2(s, lo, hi);
        sh_logit[t * 9 + 2 * p]     = lo + sh_bias[2 * p];
        sh_logit[t * 9 + 2 * p + 1] = hi + sh_bias[2 * p + 1];
    }
    __syncthreads();

    // softmax stats + argmax (first-max matches jnp.argmax)
    if (tid < T_TPBK) {
        const float* l = sh_logit + tid * 9;
        float best = l[0]; int bi = 0;
#pragma unroll
        for (int e = 1; e < NE; e++) {
            float v = l[e];
            if (v > best) { best = v; bi = e; }
        }
        float ssum = 0.f;
#pragma unroll
        for (int e = 0; e < NE; e++) ssum += expf(l[e] - best);
        sh_arg[tid] = bi;
        int gt = blockIdx.x * T_TPBK + tid;
        out[(size_t)NTOK * NE + gt] = 1.0f / ssum;
        g_expert_id[gt] = (unsigned char)bi;
    }
    __syncthreads();

    // one-hot (pre-capacity) + logits: 1024 elems, 2 per thread
#pragma unroll
    for (int k = 0; k < 2; k++) {
        int idx = tid + k * T_THREADS;
        int t = idx >> 3, e = idx & 7;
        int gt = blockIdx.x * T_TPBK + t;
        out[(size_t)gt * NE + e] = (e == sh_arg[t]) ? 1.0f : 0.0f;
        out[(size_t)NTOK * NE + NTOK + (size_t)gt * NE + e] = sh_logit[t * 9 + e];
    }

    // fused capacity epilogue: last block of each group
    __threadfence();
    __syncthreads();
    __shared__ int s_last;
    if (tid == 0) {
        unsigned int v = atomicAdd(&g_cnt[blockIdx.x / T_BPG], 1u);
        s_last = ((v & (T_BPG - 1)) == (T_BPG - 1));
    }
    __syncthreads();
    if (s_last) {
        __threadfence();
        capacity_epilogue(blockIdx.x / T_BPG, out);
    }
}

// ---------------------------------------------------------------------------
// Fallback kernel (proven R8, 36.9us): used only if the tensormap encode
// entry point is unavailable. warp = 8 tokens, front-batched LDG.128.
// ---------------------------------------------------------------------------
__global__ __launch_bounds__(256, 2)
void router_fb_kernel(const float4* __restrict__ hs4,
                      const float* __restrict__ W,
                      const float* __restrict__ bias,
                      float* __restrict__ out) {
    extern __shared__ char smem[];
    u64*   shw      = (u64*)smem;
    float* sh_logit = (float*)(shw + NE * NH / 2);
    float* sh_bias  = sh_logit + 64 * 9;
    int*   sh_arg   = (int*)(sh_bias + 8);

    const int tid  = threadIdx.x;
    const int lane = tid & 31, warp = tid >> 5;

    {
        const float2* W2 = (const float2*)W;
        float* shwf = (float*)shw;
        for (int u = tid; u < NE * NH / 2; u += 256) {
            int e = u >> 10;
            int h = (u & 1023) * 2;
            float2 w = W2[u];
            int i = h >> 7, l = (h >> 2) & 31, j = h & 3;
            int p = e >> 1, pos = e & 1;
            int w0 = ((i * 16 + j * 4 + p) << 5) + l;
            int w1 = ((i * 16 + (j + 1) * 4 + p) << 5) + l;
            shwf[w0 * 2 + pos] = w.x;
            shwf[w1 * 2 + pos] = w.y;
        }
    }
    if (tid < 8) sh_bias[tid] = bias[tid];
    __syncthreads();

    const int tok0 = blockIdx.x * 64 + warp * 8;
    const float4* xp = hs4 + (size_t)tok0 * (NH / 4) + lane;

    u64 acc[8][4];
#pragma unroll
    for (int t = 0; t < 8; t++)
#pragma unroll
        for (int p = 0; p < 4; p++) acc[t][p] = 0ULL;

#pragma unroll 1
    for (int i = 0; i < 16; i++) {
        float4 xv[8];
#pragma unroll
        for (int t = 0; t < 8; t++)
            xv[t] = xp[t * (NH / 4) + i * 32];
#pragma unroll
        for (int j = 0; j < 4; j++) {
            u64 w0 = shw[((i * 16 + j * 4 + 0) << 5) + lane];
            u64 w1 = shw[((i * 16 + j * 4 + 1) << 5) + lane];
            u64 w2 = shw[((i * 16 + j * 4 + 2) << 5) + lane];
            u64 w3 = shw[((i * 16 + j * 4 + 3) << 5) + lane];
#pragma unroll
            for (int t = 0; t < 8; t++) {
                float xs = (j == 0) ? xv[t].x : (j == 1) ? xv[t].y
                         : (j == 2) ? xv[t].z : xv[t].w;
                u64 xd = dup2(xs);
                fma2(acc[t][0], xd, w0);
                fma2(acc[t][1], xd, w1);
                fma2(acc[t][2], xd, w2);
                fma2(acc[t][3], xd, w3);
            }
        }
    }

#pragma unroll
    for (int off = 16; off; off >>= 1) {
#pragma unroll
        for (int t = 0; t < 8; t++)
#pragma unroll
            for (int p = 0; p < 4; p++)
                acc[t][p] = add2(acc[t][p],
                                 __shfl_xor_sync(0xffffffffu, acc[t][p], off));
    }
    if (lane == 0) {
#pragma unroll
        for (int t = 0; t < 8; t++)
#pragma unroll
            for (int p = 0; p < 4; p++) {
                float lo, hi;
                unpack2(acc[t][p], lo, hi);
                sh_logit[(warp * 8 + t) * 9 + 2 * p]     = lo + sh_bias[2 * p];
                sh_logit[(warp * 8 + t) * 9 + 2 * p + 1] = hi + sh_bias[2 * p + 1];
            }
    }
    __syncthreads();

    if (tid < 64) {
        const float* l = sh_logit + tid * 9;
        float best = l[0]; int bi = 0;
#pragma unroll
        for (int e = 1; e < NE; e++) {
            float v = l[e];
            if (v > best) { best = v; bi = e; }
        }
        float s = 0.f;
#pragma unroll
        for (int e = 0; e < NE; e++) s += expf(l[e] - best);
        sh_arg[tid] = bi;
        int gt = blockIdx.x * 64 + tid;
        out[(size_t)NTOK * NE + gt] = 1.0f / s;
        g_expert_id[gt] = (unsigned char)bi;
    }
    __syncthreads();

#pragma unroll
    for (int k = 0; k < 2; k++) {
        int idx = tid + k * 256;
        int t = idx >> 3, e = idx & 7;
        int gt = blockIdx.x * 64 + t;
        out[(size_t)gt * NE + e] = (e == sh_arg[t]) ? 1.0f : 0.0f;
        out[(size_t)NTOK * NE + NTOK + (size_t)gt * NE + e] = sh_logit[t * 9 + e];
    }

    __threadfence();
    __syncthreads();
    __shared__ int s_last;
    if (tid == 0) {
        unsigned int v = atomicAdd(&g_cnt[blockIdx.x / 32], 1u);
        s_last = ((v & 31) == 31);
    }
    __syncthreads();
    if (s_last) {
        __threadfence();
        capacity_epilogue(blockIdx.x / 32, out);
    }
}

// ---------------------------------------------------------------------------
extern "C" void kernel_launch(void* const* d_in, const int* in_sizes, int n_in,
                              void* d_out, int out_size) {
    const float* hs = (const float*)d_in[0];   // [8, 2048, 2048] f32
    const float* W  = (const float*)d_in[1];   // [8, 2048] f32
    const float* b  = (const float*)d_in[2];   // [8] f32
    float* out = (float*)d_out;

    typedef CUresult (*EncodeFn)(
        CUtensorMap*, CUtensorMapDataType, cuuint32_t, void*,
        const cuuint64_t*, const cuuint64_t*, const cuuint32_t*,
        const cuuint32_t*, CUtensorMapInterleave, CUtensorMapSwizzle,
        CUtensorMapL2promotion, CUtensorMapFloatOOBfill);

    void* sym = nullptr;
    cudaDriverEntryPointQueryResult qres;
    bool tma_ok = false;
    CUtensorMap tmap;
    if (cudaGetDriverEntryPoint("cuTensorMapEncodeTiled", &sym,
                                cudaEnableDefault, &qres) == cudaSuccess &&
        sym != nullptr) {
        cuuint64_t dims[2]    = {NH, NTOK};
        cuuint64_t strides[1] = {NH * sizeof(float)};
        cuuint32_t box[2]     = {32, 128};       // 128B x 128 rows, SW128
        cuuint32_t es[2]      = {1, 1};
        EncodeFn encode = (EncodeFn)sym;
        CUresult r = encode(&tmap, CU_TENSOR_MAP_DATA_TYPE_FLOAT32, 2,
                            (void*)hs, dims, strides, box, es,
                            CU_TENSOR_MAP_INTERLEAVE_NONE,
                            CU_TENSOR_MAP_SWIZZLE_128B,
                            CU_TENSOR_MAP_L2_PROMOTION_L2_128B,
                            CU_TENSOR_MAP_FLOAT_OOB_FILL_NONE);
        tma_ok = (r == CUDA_SUCCESS);
    }

    if (tma_ok) {
        cudaFuncSetAttribute(router_tma_kernel,
                             cudaFuncAttributeMaxDynamicSharedMemorySize,
                             SMEM_TOTAL);
        router_tma_kernel<<<T_NBLK, T_THREADS, SMEM_TOTAL>>>(tmap, W, b, out);
    } else {
        const int smem_fb = NE * NH / 2 * 8 + 64 * 9 * 4 + 8 * 4 + 64 * 4;
        cudaFuncSetAttribute(router_fb_kernel,
                             cudaFuncAttributeMaxDynamicSharedMemorySize,
                             smem_fb);
        router_fb_kernel<<<NTOK / 64, 256, smem_fb>>>((const float4*)hs, W, b, out);
    }
}

// round 17
// speedup vs baseline: 1.2173x; 1.0055x over previous
#include <cuda_runtime.h>
#include <cuda.h>
#include <math.h>

typedef unsigned long long u64;

#define NG 8
#define NT 2048
#define NH 2048
#define NE 8
#define CAP 320
#define NTOK (NG * NT)          // 16384

// ---- TMA kernel config ----
#define T_THREADS 512
#define T_TPBK 128              // tokens per block
#define T_NBLK (NTOK / T_TPBK)  // 128 blocks -> single wave at 1 CTA/SM
#define T_BPG (T_NBLK / NG)     // 16 blocks per group (power of 2)
#define T_NITER 32              // stages of 64 h
#define T_NSTAGE 4
#define SUBB 16384              // one TMA box: 128 tokens x 128 bytes
#define STAGEB (2 * SUBB)       // 32 KB per stage (64 h)
#define SMEM_W 65536
#define STAGE_OFF SMEM_W
#define MISC_OFF (STAGE_OFF + T_NSTAGE * STAGEB)          // 196608
#define LOGIT_OFF MISC_OFF                                 // 128*9 floats
#define BIAS_OFF (LOGIT_OFF + 128 * 9 * 4)
#define ARG_OFF  (BIAS_OFF + 32)
#define MBAR_OFF ((ARG_OFF + 128 * 4 + 15) & ~15)
#define SMEM_TOTAL (MBAR_OFF + T_NSTAGE * 8)

// scratch: argmax ids; per-group completion counters (mod-tested -> no reset)
__device__ unsigned char g_expert_id[NTOK];
__device__ unsigned int  g_cnt[NG];

__device__ __forceinline__ void fma2(u64& acc, u64 a, u64 b) {
    asm("fma.rn.f32x2 %0, %1, %2, %0;" : "+l"(acc) : "l"(a), "l"(b));
}
__device__ __forceinline__ u64 add2(u64 a, u64 b) {
    u64 r; asm("add.rn.f32x2 %0, %1, %2;" : "=l"(r) : "l"(a), "l"(b));
    return r;
}
__device__ __forceinline__ u64 pack2(float lo, float hi) {
    u64 r; asm("mov.b64 %0, {%1, %2};" : "=l"(r) : "f"(lo), "f"(hi));
    return r;
}
__device__ __forceinline__ u64 dup2(float v) { return pack2(v, v); }
__device__ __forceinline__ void unpack2(u64 v, float& lo, float& hi) {
    asm("mov.b64 {%0, %1}, %2;" : "=f"(lo), "=f"(hi) : "l"(v));
}
__device__ __forceinline__ void mbar_init(unsigned mbar, unsigned count) {
    asm volatile("mbarrier.init.shared.b64 [%0], %1;" :: "r"(mbar), "r"(count)
                 : "memory");
}
__device__ __forceinline__ void mbar_expect_tx(unsigned mbar, unsigned bytes) {
    asm volatile("mbarrier.arrive.expect_tx.shared.b64 _, [%0], %1;"
                 :: "r"(mbar), "r"(bytes) : "memory");
}
__device__ __forceinline__ void mbar_wait(unsigned mbar, unsigned parity) {
    asm volatile(
        "{\n\t"
        ".reg .pred P1;\n\t"
        "WAIT_LOOP_%=:\n\t"
        "mbarrier.try_wait.parity.acquire.cta.shared::cta.b64 P1, [%0], %1, 0x989680;\n\t"
        "@P1 bra.uni WAIT_DONE_%=;\n\t"
        "bra.uni WAIT_LOOP_%=;\n\t"
        "WAIT_DONE_%=:\n\t"
        "}"
        :: "r"(mbar), "r"(parity) : "memory");
}
__device__ __forceinline__ void tma2d(unsigned dst, const CUtensorMap* map,
                                      int x, int y, unsigned mbar) {
    asm volatile(
        "cp.async.bulk.tensor.2d.shared::cta.global.tile.mbarrier::complete_tx::bytes "
        "[%0], [%1, {%2, %3}], [%4];"
        :: "r"(dst), "l"(map), "r"(x), "r"(y), "r"(mbar) : "memory");
}

// ---------------------------------------------------------------------------
// Capacity epilogue: per-group inclusive cumsum of assignments; zero
// over-capacity one-hots. First 256 threads of the block do the scan.
// ---------------------------------------------------------------------------
__device__ void capacity_epilogue(int g, float* __restrict__ out) {
    const int tid = threadIdx.x;
    const int lane = tid & 31, wrp = tid >> 5;
    __shared__ int wt[8][NE];

    u64 ids = 0;
    int c[NE], s[NE];
#pragma unroll
    for (int e = 0; e < NE; e++) { c[e] = 0; s[e] = 0; }

    if (tid < 256) {
        ids = ((const u64*)g_expert_id)[g * (NT / 8) + tid];
#pragma unroll
        for (int i = 0; i < 8; i++) {
            int e = (int)((ids >> (8 * i)) & 0xFFULL);
#pragma unroll
            for (int ee = 0; ee < NE; ee++) c[ee] += (e == ee);
        }
#pragma unroll
        for (int e = 0; e < NE; e++) s[e] = c[e];
#pragma unroll
        for (int off = 1; off < 32; off <<= 1) {
#pragma unroll
            for (int e = 0; e < NE; e++) {
                int v = __shfl_up_sync(0xffffffffu, s[e], off);
                if (lane >= off) s[e] += v;
            }
        }
        if (lane == 31) {
#pragma unroll
            for (int e = 0; e < NE; e++) wt[wrp][e] = s[e];
        }
    }
    __syncthreads();
    if (tid < NE) {
        int run = 0;
#pragma unroll
        for (int w = 0; w < 8; w++) {
            int v = wt[w][tid];
            wt[w][tid] = run;
            run += v;
        }
    }
    __syncthreads();

    if (tid < 256) {
        int base[NE];
#pragma unroll
        for (int e = 0; e < NE; e++) base[e] = (s[e] - c[e]) + wt[wrp][e];
        int run2[NE];
#pragma unroll
        for (int e = 0; e < NE; e++) run2[e] = 0;
        const size_t tok0 = (size_t)g * NT + (size_t)tid * 8;
#pragma unroll
        for (int i = 0; i < 8; i++) {
            int e = (int)((ids >> (8 * i)) & 0xFFULL);
#pragma unroll
            for (int ee = 0; ee < NE; ee++) {
                int inc = (e == ee);
                run2[ee] += inc;
                if (inc && (base[ee] + run2[ee] > CAP))
                    out[(tok0 + i) * NE + ee] = 0.0f;
            }
        }
    }
}

// ---------------------------------------------------------------------------
// TMA router kernel. x staged through a 4-deep TMA pipeline (2 UTMALDG of
// 16 KB per 32 KB stage, SW128, mbarrier completion): in-flight DRAM bytes
// are decoupled from registers and warp count. Compute: lane = token
// (lane + 32*tk, tk=0..3), warp w owns stage-local h [4w, 4w+4); x read as
// one swizzled LDS.128 per token (conflict-free phases), W smem broadcasts.
// Per-warp h-partials reduced at the end via the retired stage area.
// ---------------------------------------------------------------------------
__global__ __launch_bounds__(T_THREADS, 1)
void router_tma_kernel(const __grid_constant__ CUtensorMap tmap,
                       const float* __restrict__ W,
                       const float* __restrict__ bias,
                       float* __restrict__ out) {
    extern __shared__ __align__(1024) char smem[];
    u64*   shw      = (u64*)smem;                     // W: 64 KB, shw[h*4+p]
    float* sh_logit = (float*)(smem + LOGIT_OFF);
    float* sh_bias  = (float*)(smem + BIAS_OFF);
    int*   sh_arg   = (int*)(smem + ARG_OFF);

    const int tid  = threadIdx.x;
    const int lane = tid & 31, warp = tid >> 5;
    const unsigned smem_u = (unsigned)__cvta_generic_to_shared(smem);
    const unsigned mbar0  = smem_u + MBAR_OFF;

    // W fill: shwf[h*8 + (e>>1)*2 + (e&1)] = W[e][h]  (broadcast pair layout)
    {
        float* shwf = (float*)shw;
        const float4* W4 = (const float4*)W;
#pragma unroll
        for (int q = 0; q < 8; q++) {
            int idx4 = tid + q * T_THREADS;          // 0..4095
            float4 v = W4[idx4];
#pragma unroll
            for (int c = 0; c < 4; c++) {
                int f = idx4 * 4 + c;                // e*2048 + h
                int e = f >> 11, h = f & 2047;
                float val = (c == 0) ? v.x : (c == 1) ? v.y
                          : (c == 2) ? v.z : v.w;
                shwf[h * 8 + (e >> 1) * 2 + (e & 1)] = val;
            }
        }
    }
    if (tid < 8) sh_bias[tid] = bias[tid];
    if (tid == 0) {
#pragma unroll
        for (int s = 0; s < T_NSTAGE; s++) mbar_init(mbar0 + s * 8, 1);
    }
    asm volatile("fence.proxy.async.shared::cta;" ::: "memory");
    __syncthreads();

    const int y0 = blockIdx.x * T_TPBK;

    auto issue = [&](int s) {
        unsigned mb  = mbar0 + (s & 3) * 8;
        unsigned dst = smem_u + STAGE_OFF + (unsigned)((s & 3) * STAGEB);
        mbar_expect_tx(mb, STAGEB);
        tma2d(dst,        &tmap, s * 64,      y0, mb);
        tma2d(dst + SUBB, &tmap, s * 64 + 32, y0, mb);
    };
    if (tid == 0) {
        issue(0); issue(1); issue(2); issue(3);
    }

    u64 acc[4][4];
#pragma unroll
    for (int t = 0; t < 4; t++)
#pragma unroll
        for (int p = 0; p < 4; p++) acc[t][p] = 0ULL;

    const int sub  = warp >> 3;            // which 16KB half of the stage
    const int colb = (warp & 7) * 16;      // byte column within 128B row

#pragma unroll 1
    for (int i = 0; i < T_NITER; i++) {
        mbar_wait(mbar0 + (i & 3) * 8, (i >> 2) & 1);

        const char* st = smem + STAGE_OFF + (i & 3) * STAGEB + sub * SUBB;
        const int hbase = i * 64 + warp * 4;

        u64 wv[4][4];
#pragma unroll
        for (int hh = 0; hh < 4; hh++)
#pragma unroll
            for (int p = 0; p < 4; p++)
                wv[hh][p] = shw[(hbase + hh) * 4 + p];

#pragma unroll
        for (int tk = 0; tk < 4; tk++) {
            int t = lane + 32 * tk;
            unsigned off = (unsigned)(t * 128 + colb);
            unsigned sw  = off ^ ((off >> 3) & 0x70);
            float4 x4 = *(const float4*)(st + sw);
#pragma unroll
            for (int hh = 0; hh < 4; hh++) {
                float xs = (hh == 0) ? x4.x : (hh == 1) ? x4.y
                         : (hh == 2) ? x4.z : x4.w;
                u64 xd = dup2(xs);
                fma2(acc[tk][0], xd, wv[hh][0]);
                fma2(acc[tk][1], xd, wv[hh][1]);
                fma2(acc[tk][2], xd, wv[hh][2]);
                fma2(acc[tk][3], xd, wv[hh][3]);
            }
        }

        __syncthreads();                       // all consumed slot i&3
        if (tid == 0 && i + T_NSTAGE < T_NITER) issue(i + T_NSTAGE);
    }

    // per-warp partials -> retired stage area: part[w*512 + t*4 + p]
    {
        u64* part = (u64*)(smem + STAGE_OFF);
#pragma unroll
        for (int tk = 0; tk < 4; tk++)
#pragma unroll
            for (int p = 0; p < 4; p++)
                part[warp * (T_TPBK * 4) + (lane + 32 * tk) * 4 + p] = acc[tk][p];
    }
    __syncthreads();

    // reduce 16 warp-partials: 512 threads = (128 tokens x 4 pairs)
    {
        const u64* part = (const u64*)(smem + STAGE_OFF);
        int t = tid >> 2, p = tid & 3;
        u64 s = part[t * 4 + p];
#pragma unroll
        for (int w = 1; w < 16; w++)
            s = add2(s, part[w * (T_TPBK * 4) + t * 4 + p]);
        float lo, hi;
        unpack2(s, lo, hi);
        sh_logit[t * 9 + 2 * p]     = lo + sh_bias[2 * p];
        sh_logit[t * 9 + 2 * p + 1] = hi + sh_bias[2 * p + 1];
    }
    __syncthreads();

    // softmax stats + argmax (first-max matches jnp.argmax)
    if (tid < T_TPBK) {
        const float* l = sh_logit + tid * 9;
        float best = l[0]; int bi = 0;
#pragma unroll
        for (int e = 1; e < NE; e++) {
            float v = l[e];
            if (v > best) { best = v; bi = e; }
        }
        float ssum = 0.f;
#pragma unroll
        for (int e = 0; e < NE; e++) ssum += expf(l[e] - best);
        sh_arg[tid] = bi;
        int gt = blockIdx.x * T_TPBK + tid;
        out[(size_t)NTOK * NE + gt] = 1.0f / ssum;
        g_expert_id[gt] = (unsigned char)bi;
    }
    __syncthreads();

    // one-hot (pre-capacity) + logits: 1024 elems, 2 per thread
#pragma unroll
    for (int k = 0; k < 2; k++) {
        int idx = tid + k * T_THREADS;
        int t = idx >> 3, e = idx & 7;
        int gt = blockIdx.x * T_TPBK + t;
        out[(size_t)gt * NE + e] = (e == sh_arg[t]) ? 1.0f : 0.0f;
        out[(size_t)NTOK * NE + NTOK + (size_t)gt * NE + e] = sh_logit[t * 9 + e];
    }

    // fused capacity epilogue: last block of each group
    __threadfence();
    __syncthreads();
    __shared__ int s_last;
    if (tid == 0) {
        unsigned int v = atomicAdd(&g_cnt[blockIdx.x / T_BPG], 1u);
        s_last = ((v & (T_BPG - 1)) == (T_BPG - 1));
    }
    __syncthreads();
    if (s_last) {
        __threadfence();
        capacity_epilogue(blockIdx.x / T_BPG, out);
    }
}

// ---------------------------------------------------------------------------
// Fallback kernel (proven R8, 36.9us): used only if the tensormap encode
// entry point is unavailable. warp = 8 tokens, front-batched LDG.128.
// ---------------------------------------------------------------------------
__global__ __launch_bounds__(256, 2)
void router_fb_kernel(const float4* __restrict__ hs4,
                      const float* __restrict__ W,
                      const float* __restrict__ bias,
                      float* __restrict__ out) {
    extern __shared__ char smem[];
    u64*   shw      = (u64*)smem;
    float* sh_logit = (float*)(shw + NE * NH / 2);
    float* sh_bias  = sh_logit + 64 * 9;
    int*   sh_arg   = (int*)(sh_bias + 8);

    const int tid  = threadIdx.x;
    const int lane = tid & 31, warp = tid >> 5;

    {
        const float2* W2 = (const float2*)W;
        float* shwf = (float*)shw;
        for (int u = tid; u < NE * NH / 2; u += 256) {
            int e = u >> 10;
            int h = (u & 1023) * 2;
            float2 w = W2[u];
            int i = h >> 7, l = (h >> 2) & 31, j = h & 3;
            int p = e >> 1, pos = e & 1;
            int w0 = ((i * 16 + j * 4 + p) << 5) + l;
            int w1 = ((i * 16 + (j + 1) * 4 + p) << 5) + l;
            shwf[w0 * 2 + pos] = w.x;
            shwf[w1 * 2 + pos] = w.y;
        }
    }
    if (tid < 8) sh_bias[tid] = bias[tid];
    __syncthreads();

    const int tok0 = blockIdx.x * 64 + warp * 8;
    const float4* xp = hs4 + (size_t)tok0 * (NH / 4) + lane;

    u64 acc[8][4];
#pragma unroll
    for (int t = 0; t < 8; t++)
#pragma unroll
        for (int p = 0; p < 4; p++) acc[t][p] = 0ULL;

#pragma unroll 1
    for (int i = 0; i < 16; i++) {
        float4 xv[8];
#pragma unroll
        for (int t = 0; t < 8; t++)
            xv[t] = xp[t * (NH / 4) + i * 32];
#pragma unroll
        for (int j = 0; j < 4; j++) {
            u64 w0 = shw[((i * 16 + j * 4 + 0) << 5) + lane];
            u64 w1 = shw[((i * 16 + j * 4 + 1) << 5) + lane];
            u64 w2 = shw[((i * 16 + j * 4 + 2) << 5) + lane];
            u64 w3 = shw[((i * 16 + j * 4 + 3) << 5) + lane];
#pragma unroll
            for (int t = 0; t < 8; t++) {
                float xs = (j == 0) ? xv[t].x : (j == 1) ? xv[t].y
                         : (j == 2) ? xv[t].z : xv[t].w;
                u64 xd = dup2(xs);
                fma2(acc[t][0], xd, w0);
                fma2(acc[t][1], xd, w1);
                fma2(acc[t][2], xd, w2);
                fma2(acc[t][3], xd, w3);
            }
        }
    }

#pragma unroll
    for (int off = 16; off; off >>= 1) {
#pragma unroll
        for (int t = 0; t < 8; t++)
#pragma unroll
            for (int p = 0; p < 4; p++)
                acc[t][p] = add2(acc[t][p],
                                 __shfl_xor_sync(0xffffffffu, acc[t][p], off));
    }
    if (lane == 0) {
#pragma unroll
        for (int t = 0; t < 8; t++)
#pragma unroll
            for (int p = 0; p < 4; p++) {
                float lo, hi;
                unpack2(acc[t][p], lo, hi);
                sh_logit[(warp * 8 + t) * 9 + 2 * p]     = lo + sh_bias[2 * p];
                sh_logit[(warp * 8 + t) * 9 + 2 * p + 1] = hi + sh_bias[2 * p + 1];
            }
    }
    __syncthreads();

    if (tid < 64) {
        const float* l = sh_logit + tid * 9;
        float best = l[0]; int bi = 0;
#pragma unroll
        for (int e = 1; e < NE; e++) {
            float v = l[e];
            if (v > best) { best = v; bi = e; }
        }
        float s = 0.f;
#pragma unroll
        for (int e = 0; e < NE; e++) s += expf(l[e] - best);
        sh_arg[tid] = bi;
        int gt = blockIdx.x * 64 + tid;
        out[(size_t)NTOK * NE + gt] = 1.0f / s;
        g_expert_id[gt] = (unsigned char)bi;
    }
    __syncthreads();

#pragma unroll
    for (int k = 0; k < 2; k++) {
        int idx = tid + k * 256;
        int t = idx >> 3, e = idx & 7;
        int gt = blockIdx.x * 64 + t;
        out[(size_t)gt * NE + e] = (e == sh_arg[t]) ? 1.0f : 0.0f;
        out[(size_t)NTOK * NE + NTOK + (size_t)gt * NE + e] = sh_logit[t * 9 + e];
    }

    __threadfence();
    __syncthreads();
    __shared__ int s_last;
    if (tid == 0) {
        unsigned int v = atomicAdd(&g_cnt[blockIdx.x / 32], 1u);
        s_last = ((v & 31) == 31);
    }
    __syncthreads();
    if (s_last) {
        __threadfence();
        capacity_epilogue(blockIdx.x / 32, out);
    }
}

// ---------------------------------------------------------------------------
extern "C" void kernel_launch(void* const* d_in, const int* in_sizes, int n_in,
                              void* d_out, int out_size) {
    const float* hs = (const float*)d_in[0];   // [8, 2048, 2048] f32
    const float* W  = (const float*)d_in[1];   // [8, 2048] f32
    const float* b  = (const float*)d_in[2];   // [8] f32
    float* out = (float*)d_out;

    typedef CUresult (*EncodeFn)(
        CUtensorMap*, CUtensorMapDataType, cuuint32_t, void*,
        const cuuint64_t*, const cuuint64_t*, const cuuint32_t*,
        const cuuint32_t*, CUtensorMapInterleave, CUtensorMapSwizzle,
        CUtensorMapL2promotion, CUtensorMapFloatOOBfill);

    void* sym = nullptr;
    cudaDriverEntryPointQueryResult qres;
    bool tma_ok = false;
    CUtensorMap tmap;
    if (cudaGetDriverEntryPoint("cuTensorMapEncodeTiled", &sym,
                                cudaEnableDefault, &qres) == cudaSuccess &&
        sym != nullptr) {
        cuuint64_t dims[2]    = {NH, NTOK};
        cuuint64_t strides[1] = {NH * sizeof(float)};
        cuuint32_t box[2]     = {32, 128};       // 128B x 128 rows, SW128
        cuuint32_t es[2]      = {1, 1};
        EncodeFn encode = (EncodeFn)sym;
        CUresult r = encode(&tmap, CU_TENSOR_MAP_DATA_TYPE_FLOAT32, 2,
                            (void*)hs, dims, strides, box, es,
                            CU_TENSOR_MAP_INTERLEAVE_NONE,
                            CU_TENSOR_MAP_SWIZZLE_128B,
                            CU_TENSOR_MAP_L2_PROMOTION_L2_128B,
                            CU_TENSOR_MAP_FLOAT_OOB_FILL_NONE);
        tma_ok = (r == CUDA_SUCCESS);
    }

    if (tma_ok) {
        cudaFuncSetAttribute(router_tma_kernel,
                             cudaFuncAttributeMaxDynamicSharedMemorySize,
                             SMEM_TOTAL);
        router_tma_kernel<<<T_NBLK, T_THREADS, SMEM_TOTAL>>>(tmap, W, b, out);
    } else {
        const int smem_fb = NE * NH / 2 * 8 + 64 * 9 * 4 + 8 * 4 + 64 * 4;
        cudaFuncSetAttribute(router_fb_kernel,
                             cudaFuncAttributeMaxDynamicSharedMemorySize,
                             smem_fb);
        router_fb_kernel<<<NTOK / 64, 256, smem_fb>>>((const float4*)hs, W, b, out);
    }
}